// round 9
// baseline (speedup 1.0000x reference)
#include <cuda_runtime.h>
#include <cuda_bf16.h>
#include <cstdint>
#include <cstddef>

#define T_LEN 16384
#define NTOT  131072
#define NBLK  16

// ---------------- activation planes (bf16 hi/lo), time-major [n][ch] ----------------
__device__ __align__(16) __nv_bfloat16 g_Xh[2][(size_t)NTOT * 128];  // ping-pong residual
__device__ __align__(16) __nv_bfloat16 g_Xl[2][(size_t)NTOT * 128];
__device__ __align__(16) __nv_bfloat16 g_Zh[(size_t)NBLK * NTOT * 128];
__device__ __align__(16) __nv_bfloat16 g_Zl[(size_t)NBLK * NTOT * 128];
__device__ __align__(16) __nv_bfloat16 g_Sh[(size_t)NTOT * 256];
__device__ __align__(16) __nv_bfloat16 g_Sl[(size_t)NTOT * 256];
__device__ __align__(16) __nv_bfloat16 g_Hh[(size_t)NTOT * 256];
__device__ __align__(16) __nv_bfloat16 g_Hl[(size_t)NTOT * 256];

// weight blocks: [plane2][row128][k16] bf16 = 4096 elems per block
__device__ __align__(16) __nv_bfloat16 g_WFG[(size_t)NBLK * 2 * 16 * 4096];
__device__ __align__(16) __nv_bfloat16 g_WRS[(size_t)NBLK * 8 * 4096];
__device__ __align__(16) __nv_bfloat16 g_WSK[(size_t)2 * 128 * 4096];
__device__ __align__(16) __nv_bfloat16 g_W1b[(size_t)2 * 16 * 4096];
__device__ __align__(16) __nv_bfloat16 g_W2b[(size_t)2 * 16 * 4096];
__device__ float g_Bsk[256];

// ---------------- helpers ----------------
__device__ __forceinline__ uint32_t smem_u32(const void* p) {
    uint32_t a;
    asm("{ .reg .u64 t; cvta.to.shared.u64 t, %1; cvt.u32.u64 %0, t; }" : "=r"(a) : "l"(p));
    return a;
}
__device__ __forceinline__ void bsplit(float v, __nv_bfloat16& h, __nv_bfloat16& l) {
    h = __float2bfloat16(v);
    l = __float2bfloat16(v - __bfloat162float(h));
}
__device__ __forceinline__ void store2(__nv_bfloat16* Ph, __nv_bfloat16* Pl, size_t off,
                                       float v0, float v1) {
    __nv_bfloat16 h0, l0, h1, l1;
    bsplit(v0, h0, l0); bsplit(v1, h1, l1);
    __nv_bfloat162 hp; hp.x = h0; hp.y = h1;
    __nv_bfloat162 lp; lp.x = l0; lp.y = l1;
    *reinterpret_cast<__nv_bfloat162*>(Ph + off) = hp;
    *reinterpret_cast<__nv_bfloat162*>(Pl + off) = lp;
}
__device__ __forceinline__ float safe_tanh(float x) {
    float ax = fabsf(x);
    float e = __expf(-2.0f * ax);
    return copysignf((1.0f - e) / (1.0f + e), x);
}
__device__ __forceinline__ float sigmoidf_(float x) { return 1.0f / (1.0f + __expf(-x)); }

// ---------------- packing (unchanged from R8) ----------------
__global__ void pack_fg(const float* __restrict__ Wf, const float* __restrict__ Wg) {
    int idx = blockIdx.x * blockDim.x + threadIdx.x;
    int kin = idx & 15, row = (idx >> 4) & 127, c = (idx >> 11) & 15;
    int nt = (idx >> 15) & 1, l = idx >> 16;
    int m = nt * 128 + row, ch = m >> 1, isg = m & 1;
    int tap = (c < 8) ? 1 : 0;
    int cin = (c & 7) * 16 + kin;
    float v = 0.f;
    if (ch < 120 && cin < 120) {
        const float* s = isg ? Wg : Wf;
        v = s[(((size_t)l * 120 + ch) * 120 + cin) * 2 + tap];
    }
    __nv_bfloat16 h, lo; bsplit(v, h, lo);
    __nv_bfloat16* blk = g_WFG + ((size_t)((l * 2 + nt) * 16 + c)) * 4096;
    blk[row * 16 + kin] = h;
    blk[2048 + row * 16 + kin] = lo;
}

__global__ void pack_rs(const float* __restrict__ Wres) {
    int idx = blockIdx.x * blockDim.x + threadIdx.x;
    int kin = idx & 15, row = (idx >> 4) & 127, c = (idx >> 11) & 7, l = idx >> 14;
    int cin = c * 16 + kin;
    float v = (row < 120 && cin < 120) ? Wres[((size_t)l * 120 + row) * 120 + cin] : 0.f;
    __nv_bfloat16 h, lo; bsplit(v, h, lo);
    __nv_bfloat16* blk = g_WRS + ((size_t)(l * 8 + c)) * 4096;
    blk[row * 16 + kin] = h;
    blk[2048 + row * 16 + kin] = lo;
}

__global__ void pack_sk(const float* __restrict__ Wskip, const float* __restrict__ bskip) {
    int idx = blockIdx.x * blockDim.x + threadIdx.x;
    int kin = idx & 15, row = (idx >> 4) & 127, c = (idx >> 11) & 127, nt = idx >> 18;
    int q = nt * 128 + row, lay = c >> 3, cin = (c & 7) * 16 + kin;
    float v = (q < 240 && cin < 120) ? Wskip[((size_t)lay * 240 + q) * 120 + cin] : 0.f;
    __nv_bfloat16 h, lo; bsplit(v, h, lo);
    __nv_bfloat16* blk = g_WSK + ((size_t)(nt * 128 + c)) * 4096;
    blk[row * 16 + kin] = h;
    blk[2048 + row * 16 + kin] = lo;
    if (idx < 256) {
        float s = 0.f;
        if (idx < 240) for (int j = 0; j < NBLK; j++) s += bskip[j * 240 + idx];
        g_Bsk[idx] = s;
    }
}

__global__ void pack_h(const float* __restrict__ W1, const float* __restrict__ W2) {
    int idx = blockIdx.x * blockDim.x + threadIdx.x;
    int kin = idx & 15, row = (idx >> 4) & 127, c = (idx >> 11) & 15, nt = idx >> 15;
    int q = nt * 128 + row, k = c * 16 + kin;
    float v1 = (k < 240) ? W1[(size_t)q * 240 + k] : 0.f;
    float v2 = W2[(size_t)q * 256 + k];
    __nv_bfloat16 h, lo;
    __nv_bfloat16* b1 = g_W1b + ((size_t)(nt * 16 + c)) * 4096;
    __nv_bfloat16* b2 = g_W2b + ((size_t)(nt * 16 + c)) * 4096;
    bsplit(v1, h, lo); b1[row * 16 + kin] = h; b1[2048 + row * 16 + kin] = lo;
    bsplit(v2, h, lo); b2[row * 16 + kin] = h; b2[2048 + row * 16 + kin] = lo;
}

__global__ void init_kernel(const float* __restrict__ wave,
                            const float* __restrict__ W_in,
                            const float* __restrict__ b_in) {
    int idx = blockIdx.x * blockDim.x + threadIdx.x;
    int n = idx >> 7, c = idx & 127;
    float x = (c < 120) ? (W_in[c] * wave[n] + b_in[c]) : 0.f;
    __nv_bfloat16 h, l; bsplit(x, h, l);
    g_Xh[0][idx] = h; g_Xl[0][idx] = l;
}

// ---------------- asm macros ----------------
#define CPA16(dst, src, sz) \
    asm volatile("cp.async.cg.shared.global [%0], [%1], 16, %2;" \
                 :: "r"(dst), "l"(src), "r"(sz) : "memory")
#define CP_COMMIT() asm volatile("cp.async.commit_group;" ::: "memory")
#define CP_WAIT2()  asm volatile("cp.async.wait_group 2;" ::: "memory")

#define LDM4(rr, addr) \
    asm volatile("ldmatrix.sync.aligned.m8n8.x4.shared.b16 {%0,%1,%2,%3}, [%4];" \
                 : "=r"((rr)[0]), "=r"((rr)[1]), "=r"((rr)[2]), "=r"((rr)[3]) : "r"(addr))

#define MMA(cr, a, b0v, b1v) \
    asm volatile("mma.sync.aligned.m16n8k16.row.col.f32.bf16.bf16.f32 " \
                 "{%0,%1,%2,%3}, {%4,%5,%6,%7}, {%8,%9}, {%0,%1,%2,%3};" \
                 : "+f"((cr)[0]), "+f"((cr)[1]), "+f"((cr)[2]), "+f"((cr)[3]) \
                 : "r"((a)[0]), "r"((a)[1]), "r"((a)[2]), "r"((a)[3]), "r"(b0v), "r"(b1v))

// ---------------- fused FG + RES kernel: CTA 128(time) x 256(col), 512 thr ----------------
// Stage slot (36864B): Ah@0(6144) Al@6144 Wh@12288(12288) Wl@24576. 4 stages.
// z tile: hi@147456, lo@147456+34816. pitch 272.
#define SLOT  36864u
#define ZOFF  147456u
#define ZPIT  272u
#define ZPL   34816u
#define FS_BYTES (147456 + 69632)

__global__ void __launch_bounds__(512, 1) fgres_kernel(int layer, int dil,
        const float* __restrict__ bf, const float* __restrict__ bg,
        const float* __restrict__ bres) {
    extern __shared__ __align__(16) char sm[];
    const int tid = threadIdx.x, lane = tid & 31, wid = tid >> 5;
    const int wn = wid >> 3, wc = wid & 7;      // 2 time-groups(64) x 8 col-groups(32)
    const int n0 = blockIdx.x * 128;
    const uint32_t smb = smem_u32(sm);

    const __nv_bfloat16* Xrh = g_Xh[layer & 1];
    const __nv_bfloat16* Xrl = g_Xl[layer & 1];
    __nv_bfloat16* Xwh = g_Xh[(layer + 1) & 1];
    __nv_bfloat16* Xwl = g_Xl[(layer + 1) & 1];
    const __nv_bfloat16* Wb  = g_WFG + (size_t)layer * 2 * 16 * 4096;
    const __nv_bfloat16* WRb = g_WRS + (size_t)layer * 8 * 4096;

    uint32_t offA[4], offB[2], offRB;
    {
        int rA = wn * 64 + (lane & 15);
        int cA = (lane >> 4) * 16;
#pragma unroll
        for (int i = 0; i < 4; i++) offA[i] = (uint32_t)((rA + i * 16) * 48 + cA);
        int rB = wc * 32 + (lane >> 4) * 8 + (lane & 7);
        int cB = ((lane >> 3) & 1) * 16;
        offB[0] = (uint32_t)(rB * 48 + cB);
        offB[1] = (uint32_t)((rB + 16) * 48 + cB);
        int rR = wc * 16 + (lane >> 4) * 8 + (lane & 7);
        offRB = (uint32_t)(rR * 48 + cB);
    }

    float acc[4][4][4];
#pragma unroll
    for (int i = 0; i < 4; i++)
#pragma unroll
        for (int j = 0; j < 4; j++)
#pragma unroll
            for (int k = 0; k < 4; k++) acc[i][j][k] = 0.f;

#define FSTAGE(cc, s) do {                                                        \
        {   /* A: 128 rows x 16k x 2 planes = 8KB, 1 cp per thread */             \
            int u = tid, p = u >> 8, r = (u >> 1) & 127, hh = u & 1;              \
            int na = n0 + r, nn = na, sz = 16, ch0;                               \
            if ((cc) < 8) ch0 = (cc) * 16;                                        \
            else {                                                                \
                ch0 = ((cc) - 8) * 16;                                            \
                int t = na & (T_LEN - 1);                                         \
                if (t >= dil) nn = na - dil; else sz = 0;                         \
            }                                                                     \
            uint32_t d = smb + (s) * SLOT + p * 6144u + r * 48u + hh * 16u;       \
            const __nv_bfloat16* gp = (p ? Xrl : Xrh) + (size_t)nn * 128 + ch0 + hh * 8; \
            CPA16(d, gp, sz);                                                     \
        }                                                                         \
        _Pragma("unroll")                                                         \
        for (int ii = 0; ii < 2; ii++) {   /* W: 256 rows x 16k x 2 pl = 16KB */  \
            int u = tid + ii * 512, p = (u >> 9) & 1, r = (u >> 1) & 255, hh = u & 1; \
            uint32_t d = smb + (s) * SLOT + 12288u + p * 12288u + r * 48u + hh * 16u; \
            const __nv_bfloat16* sp = Wb + ((size_t)((r >> 7) * 16 + (cc))) * 4096 \
                                      + p * 2048 + (r & 127) * 16 + hh * 8;       \
            CPA16(d, sp, 16);                                                     \
        }                                                                         \
    } while (0)

    FSTAGE(0, 0); CP_COMMIT();
    FSTAGE(1, 1); CP_COMMIT();
    FSTAGE(2, 2); CP_COMMIT();

#pragma unroll 1
    for (int c = 0; c < 16; c++) {
        CP_WAIT2();
        __syncthreads();
        if (c + 3 < 16) FSTAGE(c + 3, (c + 3) & 3);
        CP_COMMIT();

        const uint32_t base = smb + (uint32_t)(c & 3) * SLOT;
        uint32_t Ah[4][4], Al[4][4], Bf[2][4];
#pragma unroll
        for (int i = 0; i < 4; i++) {
            LDM4(Ah[i], base + offA[i]);
            LDM4(Al[i], base + 6144u + offA[i]);
        }
        LDM4(Bf[0], base + 12288u + offB[0]);
        LDM4(Bf[1], base + 12288u + offB[1]);
#pragma unroll
        for (int i = 0; i < 4; i++)
#pragma unroll
            for (int j = 0; j < 4; j++)
                MMA(acc[i][j], Ah[i], Bf[j >> 1][(j & 1) * 2], Bf[j >> 1][(j & 1) * 2 + 1]);
#pragma unroll
        for (int i = 0; i < 4; i++)
#pragma unroll
            for (int j = 0; j < 4; j++)
                MMA(acc[i][j], Al[i], Bf[j >> 1][(j & 1) * 2], Bf[j >> 1][(j & 1) * 2 + 1]);
        LDM4(Bf[0], base + 24576u + offB[0]);
        LDM4(Bf[1], base + 24576u + offB[1]);
#pragma unroll
        for (int i = 0; i < 4; i++)
#pragma unroll
            for (int j = 0; j < 4; j++)
                MMA(acc[i][j], Ah[i], Bf[j >> 1][(j & 1) * 2], Bf[j >> 1][(j & 1) * 2 + 1]);
    }
#undef FSTAGE

    // prefetch RES W (overlaps z epilogue). Stage: Wh@0(6144) Wl@6144.
#define RSTAGE(rc, s) do {                                                        \
        int u = tid, p = u >> 8, r = (u >> 1) & 127, hh = u & 1;                  \
        uint32_t d = smb + (s) * SLOT + p * 6144u + r * 48u + hh * 16u;           \
        const __nv_bfloat16* sp = WRb + (size_t)(rc) * 4096 + p * 2048 + r * 16 + hh * 8; \
        CPA16(d, sp, 16);                                                         \
    } while (0)

    __syncthreads();   // all FG reads of stage slots done before RES W overwrites
    RSTAGE(0, 0); CP_COMMIT();
    RSTAGE(1, 1); CP_COMMIT();
    RSTAGE(2, 2); CP_COMMIT();

    // ---- epilogue 1: z = tanh(f+bf)*sigmoid(g+bg) -> SMEM z tile + gmem ----
#pragma unroll
    for (int j = 0; j < 4; j++) {
        int c0 = wc * 32 + j * 8 + (lane & 3) * 2;
        int ch = c0 >> 1;
        float bfv = 0.f, bgv = 0.f;
        if (ch < 120) { bfv = bf[layer * 120 + ch]; bgv = bg[layer * 120 + ch]; }
#pragma unroll
        for (int i = 0; i < 4; i++)
#pragma unroll
            for (int h = 0; h < 2; h++) {
                int row = wn * 64 + i * 16 + h * 8 + (lane >> 2);
                float z = safe_tanh(acc[i][j][h * 2] + bfv) *
                          sigmoidf_(acc[i][j][h * 2 + 1] + bgv);
                __nv_bfloat16 zh, zl; bsplit(z, zh, zl);
                *reinterpret_cast<__nv_bfloat16*>(sm + ZOFF + row * ZPIT + ch * 2) = zh;
                *reinterpret_cast<__nv_bfloat16*>(sm + ZOFF + ZPL + row * ZPIT + ch * 2) = zl;
                size_t off = (size_t)layer * NTOT * 128 + (size_t)(n0 + row) * 128 + ch;
                g_Zh[off] = zh; g_Zl[off] = zl;
            }
    }

    // ---- RES GEMM: racc[128t x 128ch] = z @ Wres^T (z from SMEM) ----
    float racc[4][2][4];
#pragma unroll
    for (int i = 0; i < 4; i++)
#pragma unroll
        for (int j = 0; j < 2; j++)
#pragma unroll
            for (int k = 0; k < 4; k++) racc[i][j][k] = 0.f;

#pragma unroll 1
    for (int rc = 0; rc < 8; rc++) {
        CP_WAIT2();
        __syncthreads();
        if (rc + 3 < 8) RSTAGE(rc + 3, (rc + 3) & 3);
        CP_COMMIT();

        const uint32_t base = smb + (uint32_t)(rc & 3) * SLOT;
        uint32_t ZAh[4][4], ZAl[4][4], RB[4];
        uint32_t zk = (uint32_t)(rc * 32) + (lane >> 4) * 16;
#pragma unroll
        for (int i = 0; i < 4; i++) {
            uint32_t zr = smb + ZOFF + (wn * 64 + i * 16 + (lane & 15)) * ZPIT + zk;
            LDM4(ZAh[i], zr);
            LDM4(ZAl[i], zr + ZPL);
        }
        LDM4(RB, base + offRB);
#pragma unroll
        for (int i = 0; i < 4; i++)
#pragma unroll
            for (int j = 0; j < 2; j++)
                MMA(racc[i][j], ZAh[i], RB[j * 2], RB[j * 2 + 1]);
#pragma unroll
        for (int i = 0; i < 4; i++)
#pragma unroll
            for (int j = 0; j < 2; j++)
                MMA(racc[i][j], ZAl[i], RB[j * 2], RB[j * 2 + 1]);
        LDM4(RB, base + 6144u + offRB);
#pragma unroll
        for (int i = 0; i < 4; i++)
#pragma unroll
            for (int j = 0; j < 2; j++)
                MMA(racc[i][j], ZAh[i], RB[j * 2], RB[j * 2 + 1]);
    }
#undef RSTAGE

    // ---- epilogue 2: X_next = X_cur + res + bres ----
#pragma unroll
    for (int j = 0; j < 2; j++) {
        int col = wc * 16 + j * 8 + (lane & 3) * 2;
        if (col < 120) {
            float bv0 = bres[layer * 120 + col];
            float bv1 = bres[layer * 120 + col + 1];
#pragma unroll
            for (int i = 0; i < 4; i++)
#pragma unroll
                for (int h = 0; h < 2; h++) {
                    int row = n0 + wn * 64 + i * 16 + h * 8 + (lane >> 2);
                    size_t off = (size_t)row * 128 + col;
                    __nv_bfloat162 xh = *reinterpret_cast<const __nv_bfloat162*>(Xrh + off);
                    __nv_bfloat162 xl = *reinterpret_cast<const __nv_bfloat162*>(Xrl + off);
                    float x0 = __bfloat162float(xh.x) + __bfloat162float(xl.x)
                             + racc[i][j][h * 2] + bv0;
                    float x1 = __bfloat162float(xh.y) + __bfloat162float(xl.y)
                             + racc[i][j][h * 2 + 1] + bv1;
                    store2(Xwh, Xwl, off, x0, x1);
                }
        }
    }
}

// ---------------- generic GEMM (SKIP / H1 / H2): CTA 128 x 256, 512 thr ----------------
template<int MODE, int NCH>
__global__ void __launch_bounds__(512, 1) mma_kernel(const float* __restrict__ bA,
                                                     float* __restrict__ dout) {
    extern __shared__ __align__(16) char sm[];
    const int tid = threadIdx.x, lane = tid & 31, wid = tid >> 5;
    const int wn = wid >> 3, wc = wid & 7;
    const int n0 = blockIdx.x * 128;
    const uint32_t smb = smem_u32(sm);

    const __nv_bfloat16 *Wfam, *APh, *APl;
    int NB, CHW;
    if (MODE == 2)      { Wfam = g_WSK; NB = 128; APh = g_Zh; APl = g_Zl; CHW = 128; }
    else if (MODE == 3) { Wfam = g_W1b; NB = 16;  APh = g_Sh; APl = g_Sl; CHW = 256; }
    else                { Wfam = g_W2b; NB = 16;  APh = g_Hh; APl = g_Hl; CHW = 256; }

    uint32_t offA[4], offB[2];
    {
        int rA = wn * 64 + (lane & 15);
        int cA = (lane >> 4) * 16;
#pragma unroll
        for (int i = 0; i < 4; i++) offA[i] = (uint32_t)((rA + i * 16) * 48 + cA);
        int rB = wc * 32 + (lane >> 4) * 8 + (lane & 7);
        int cB = ((lane >> 3) & 1) * 16;
        offB[0] = (uint32_t)(rB * 48 + cB);
        offB[1] = (uint32_t)((rB + 16) * 48 + cB);
    }

    float acc[4][4][4];
#pragma unroll
    for (int i = 0; i < 4; i++)
#pragma unroll
        for (int j = 0; j < 4; j++)
#pragma unroll
            for (int k = 0; k < 4; k++) acc[i][j][k] = 0.f;

#define STAGE(cc, s) do {                                                         \
        {                                                                         \
            int u = tid, p = u >> 8, r = (u >> 1) & 127, hh = u & 1;              \
            int ch0; const __nv_bfloat16 *ah_ = APh, *al_ = APl;                  \
            if (MODE == 2) {                                                      \
                ch0 = ((cc) & 7) * 16;                                            \
                size_t zo = (size_t)((cc) >> 3) * NTOT * 128;                     \
                ah_ += zo; al_ += zo;                                             \
            } else ch0 = (cc) * 16;                                               \
            uint32_t d = smb + (s) * SLOT + p * 6144u + r * 48u + hh * 16u;       \
            const __nv_bfloat16* gp = (p ? al_ : ah_) + (size_t)(n0 + r) * CHW + ch0 + hh * 8; \
            CPA16(d, gp, 16);                                                     \
        }                                                                         \
        _Pragma("unroll")                                                         \
        for (int ii = 0; ii < 2; ii++) {                                          \
            int u = tid + ii * 512, p = (u >> 9) & 1, r = (u >> 1) & 255, hh = u & 1; \
            uint32_t d = smb + (s) * SLOT + 12288u + p * 12288u + r * 48u + hh * 16u; \
            const __nv_bfloat16* sp = Wfam + ((size_t)((r >> 7) * NB + (cc))) * 4096 \
                                      + p * 2048 + (r & 127) * 16 + hh * 8;       \
            CPA16(d, sp, 16);                                                     \
        }                                                                         \
    } while (0)

    STAGE(0, 0); CP_COMMIT();
    STAGE(1, 1); CP_COMMIT();
    STAGE(2, 2); CP_COMMIT();

#pragma unroll 1
    for (int c = 0; c < NCH; c++) {
        CP_WAIT2();
        __syncthreads();
        if (c + 3 < NCH) STAGE(c + 3, (c + 3) & 3);
        CP_COMMIT();

        const uint32_t base = smb + (uint32_t)(c & 3) * SLOT;
        uint32_t Ah[4][4], Al[4][4], Bf[2][4];
#pragma unroll
        for (int i = 0; i < 4; i++) {
            LDM4(Ah[i], base + offA[i]);
            LDM4(Al[i], base + 6144u + offA[i]);
        }
        LDM4(Bf[0], base + 12288u + offB[0]);
        LDM4(Bf[1], base + 12288u + offB[1]);
#pragma unroll
        for (int i = 0; i < 4; i++)
#pragma unroll
            for (int j = 0; j < 4; j++)
                MMA(acc[i][j], Ah[i], Bf[j >> 1][(j & 1) * 2], Bf[j >> 1][(j & 1) * 2 + 1]);
#pragma unroll
        for (int i = 0; i < 4; i++)
#pragma unroll
            for (int j = 0; j < 4; j++)
                MMA(acc[i][j], Al[i], Bf[j >> 1][(j & 1) * 2], Bf[j >> 1][(j & 1) * 2 + 1]);
        LDM4(Bf[0], base + 24576u + offB[0]);
        LDM4(Bf[1], base + 24576u + offB[1]);
#pragma unroll
        for (int i = 0; i < 4; i++)
#pragma unroll
            for (int j = 0; j < 4; j++)
                MMA(acc[i][j], Ah[i], Bf[j >> 1][(j & 1) * 2], Bf[j >> 1][(j & 1) * 2 + 1]);
    }
#undef STAGE

#pragma unroll
    for (int j = 0; j < 4; j++) {
        const int col = wc * 32 + j * 8 + (lane & 3) * 2;
        float bv0, bv1;
        if (MODE == 2) { bv0 = g_Bsk[col]; bv1 = g_Bsk[col + 1]; }
        else           { bv0 = bA[col]; bv1 = bA[col + 1]; }
#pragma unroll
        for (int i = 0; i < 4; i++)
#pragma unroll
            for (int h = 0; h < 2; h++) {
                int na = n0 + wn * 64 + i * 16 + h * 8 + (lane >> 2);
                float v0 = acc[i][j][h * 2], v1 = acc[i][j][h * 2 + 1];
                if (MODE == 2) {
                    store2(g_Sh, g_Sl, (size_t)na * 256 + col,
                           fmaxf(v0 + bv0, 0.f), fmaxf(v1 + bv1, 0.f));
                } else if (MODE == 3) {
                    store2(g_Hh, g_Hl, (size_t)na * 256 + col,
                           fmaxf(v0 + bv0, 0.f), fmaxf(v1 + bv1, 0.f));
                } else {
                    int b = na >> 14, t = na & (T_LEN - 1);
                    dout[((size_t)b * 256 + col) * T_LEN + t]     = v0 + bv0;
                    dout[((size_t)b * 256 + col + 1) * T_LEN + t] = v1 + bv1;
                }
            }
    }
}

// ---------------- launch ----------------
extern "C" void kernel_launch(void* const* d_in, const int* in_sizes, int n_in,
                              void* d_out, int out_size) {
    const float* wave  = (const float*)d_in[0];
    const float* W_in  = (const float*)d_in[1];
    const float* b_in  = (const float*)d_in[2];
    const float* Wf    = (const float*)d_in[3];
    const float* bf    = (const float*)d_in[4];
    const float* Wg    = (const float*)d_in[5];
    const float* bg    = (const float*)d_in[6];
    const float* Wres  = (const float*)d_in[7];
    const float* bres  = (const float*)d_in[8];
    const float* Wskip = (const float*)d_in[9];
    const float* bskip = (const float*)d_in[10];
    const float* W1    = (const float*)d_in[11];
    const float* b1    = (const float*)d_in[12];
    const float* W2    = (const float*)d_in[13];
    const float* b2    = (const float*)d_in[14];
    float* out = (float*)d_out;

    const int GS = 4 * SLOT;   // 147456 for generic kernels
    cudaFuncSetAttribute(fgres_kernel, cudaFuncAttributeMaxDynamicSharedMemorySize, FS_BYTES);
    cudaFuncSetAttribute(mma_kernel<2, 128>, cudaFuncAttributeMaxDynamicSharedMemorySize, GS);
    cudaFuncSetAttribute(mma_kernel<3, 16>,  cudaFuncAttributeMaxDynamicSharedMemorySize, GS);
    cudaFuncSetAttribute(mma_kernel<4, 16>,  cudaFuncAttributeMaxDynamicSharedMemorySize, GS);

    pack_fg<<<16 * 2 * 16 * 2048 / 256, 256>>>(Wf, Wg);
    pack_rs<<<16 * 8 * 2048 / 256, 256>>>(Wres);
    pack_sk<<<2 * 128 * 2048 / 256, 256>>>(Wskip, bskip);
    pack_h <<<2 * 16 * 2048 / 256, 256>>>(W1, W2);
    init_kernel<<<(size_t)NTOT * 128 / 256, 256>>>(wave, W_in, b_in);

    static const int dil[NBLK] = {1, 2, 4, 8, 16, 32, 64, 128,
                                  1, 2, 4, 8, 16, 32, 64, 128};

    for (int i = 0; i < NBLK; i++)
        fgres_kernel<<<NTOT / 128, 512, FS_BYTES>>>(i, dil[i], bf, bg, bres);

    mma_kernel<2, 128><<<NTOT / 128, 512, GS>>>(nullptr, nullptr);  // batched skip
    mma_kernel<3, 16><<<NTOT / 128, 512, GS>>>(b1, nullptr);        // head1
    mma_kernel<4, 16><<<NTOT / 128, 512, GS>>>(b2, out);            // head2
}

// round 10
// speedup vs baseline: 1.2574x; 1.2574x over previous
#include <cuda_runtime.h>
#include <cuda_fp16.h>
#include <cstdint>
#include <cstddef>

#define T_LEN 16384
#define NTOT  131072
#define NBLK  16

// ---------------- activations, time-major [n][ch] ----------------
// X residual stream: split fp16 (hi+lo, ~2^-22 storage) — MMA uses hi plane only.
__device__ __align__(16) __half g_Xh[2][(size_t)NTOT * 128];
__device__ __align__(16) __half g_Xl[2][(size_t)NTOT * 128];
__device__ __align__(16) __half g_Z [(size_t)NBLK * NTOT * 128];   // single fp16
__device__ __align__(16) __half g_S [(size_t)NTOT * 256];
__device__ __align__(16) __half g_H [(size_t)NTOT * 256];

// weight blocks: [plane2][row128][k16] fp16 = 4096 elems per block (split: Wh, Wl)
__device__ __align__(16) __half g_WFG[(size_t)NBLK * 2 * 16 * 4096];
__device__ __align__(16) __half g_WRS[(size_t)NBLK * 8 * 4096];
__device__ __align__(16) __half g_WSK[(size_t)2 * 128 * 4096];
__device__ __align__(16) __half g_W1b[(size_t)2 * 16 * 4096];
__device__ __align__(16) __half g_W2b[(size_t)2 * 16 * 4096];
__device__ float g_Bsk[256];

// ---------------- helpers ----------------
__device__ __forceinline__ uint32_t smem_u32(const void* p) {
    uint32_t a;
    asm("{ .reg .u64 t; cvta.to.shared.u64 t, %1; cvt.u32.u64 %0, t; }" : "=r"(a) : "l"(p));
    return a;
}
__device__ __forceinline__ void hsplit(float v, __half& h, __half& l) {
    h = __float2half(v);
    l = __float2half(v - __half2float(h));
}
__device__ __forceinline__ float safe_tanh(float x) {
    float ax = fabsf(x);
    float e = __expf(-2.0f * ax);
    return copysignf((1.0f - e) / (1.0f + e), x);
}
__device__ __forceinline__ float sigmoidf_(float x) { return 1.0f / (1.0f + __expf(-x)); }

// ---------------- packing (fp16 split weights) ----------------
__global__ void pack_fg(const float* __restrict__ Wf, const float* __restrict__ Wg) {
    int idx = blockIdx.x * blockDim.x + threadIdx.x;
    int kin = idx & 15, row = (idx >> 4) & 127, c = (idx >> 11) & 15;
    int nt = (idx >> 15) & 1, l = idx >> 16;
    int m = nt * 128 + row, ch = m >> 1, isg = m & 1;
    int tap = (c < 8) ? 1 : 0;
    int cin = (c & 7) * 16 + kin;
    float v = 0.f;
    if (ch < 120 && cin < 120) {
        const float* s = isg ? Wg : Wf;
        v = s[(((size_t)l * 120 + ch) * 120 + cin) * 2 + tap];
    }
    __half h, lo; hsplit(v, h, lo);
    __half* blk = g_WFG + ((size_t)((l * 2 + nt) * 16 + c)) * 4096;
    blk[row * 16 + kin] = h;
    blk[2048 + row * 16 + kin] = lo;
}

__global__ void pack_rs(const float* __restrict__ Wres) {
    int idx = blockIdx.x * blockDim.x + threadIdx.x;
    int kin = idx & 15, row = (idx >> 4) & 127, c = (idx >> 11) & 7, l = idx >> 14;
    int cin = c * 16 + kin;
    float v = (row < 120 && cin < 120) ? Wres[((size_t)l * 120 + row) * 120 + cin] : 0.f;
    __half h, lo; hsplit(v, h, lo);
    __half* blk = g_WRS + ((size_t)(l * 8 + c)) * 4096;
    blk[row * 16 + kin] = h;
    blk[2048 + row * 16 + kin] = lo;
}

__global__ void pack_sk(const float* __restrict__ Wskip, const float* __restrict__ bskip) {
    int idx = blockIdx.x * blockDim.x + threadIdx.x;
    int kin = idx & 15, row = (idx >> 4) & 127, c = (idx >> 11) & 127, nt = idx >> 18;
    int q = nt * 128 + row, lay = c >> 3, cin = (c & 7) * 16 + kin;
    float v = (q < 240 && cin < 120) ? Wskip[((size_t)lay * 240 + q) * 120 + cin] : 0.f;
    __half h, lo; hsplit(v, h, lo);
    __half* blk = g_WSK + ((size_t)(nt * 128 + c)) * 4096;
    blk[row * 16 + kin] = h;
    blk[2048 + row * 16 + kin] = lo;
    if (idx < 256) {
        float s = 0.f;
        if (idx < 240) for (int j = 0; j < NBLK; j++) s += bskip[j * 240 + idx];
        g_Bsk[idx] = s;
    }
}

__global__ void pack_h(const float* __restrict__ W1, const float* __restrict__ W2) {
    int idx = blockIdx.x * blockDim.x + threadIdx.x;
    int kin = idx & 15, row = (idx >> 4) & 127, c = (idx >> 11) & 15, nt = idx >> 15;
    int q = nt * 128 + row, k = c * 16 + kin;
    float v1 = (k < 240) ? W1[(size_t)q * 240 + k] : 0.f;
    float v2 = W2[(size_t)q * 256 + k];
    __half h, lo;
    __half* b1 = g_W1b + ((size_t)(nt * 16 + c)) * 4096;
    __half* b2 = g_W2b + ((size_t)(nt * 16 + c)) * 4096;
    hsplit(v1, h, lo); b1[row * 16 + kin] = h; b1[2048 + row * 16 + kin] = lo;
    hsplit(v2, h, lo); b2[row * 16 + kin] = h; b2[2048 + row * 16 + kin] = lo;
}

__global__ void init_kernel(const float* __restrict__ wave,
                            const float* __restrict__ W_in,
                            const float* __restrict__ b_in) {
    int idx = blockIdx.x * blockDim.x + threadIdx.x;
    int n = idx >> 7, c = idx & 127;
    float x = (c < 120) ? (W_in[c] * wave[n] + b_in[c]) : 0.f;
    __half h, l; hsplit(x, h, l);
    g_Xh[0][idx] = h; g_Xl[0][idx] = l;
}

// ---------------- asm macros ----------------
#define CPA16(dst, src, sz) \
    asm volatile("cp.async.cg.shared.global [%0], [%1], 16, %2;" \
                 :: "r"(dst), "l"(src), "r"(sz) : "memory")
#define CP_COMMIT() asm volatile("cp.async.commit_group;" ::: "memory")
#define CP_WAIT2()  asm volatile("cp.async.wait_group 2;" ::: "memory")

#define LDM4(rr, addr) \
    asm volatile("ldmatrix.sync.aligned.m8n8.x4.shared.b16 {%0,%1,%2,%3}, [%4];" \
                 : "=r"((rr)[0]), "=r"((rr)[1]), "=r"((rr)[2]), "=r"((rr)[3]) : "r"(addr))

#define MMA(cr, a, b0v, b1v) \
    asm volatile("mma.sync.aligned.m16n8k16.row.col.f32.f16.f16.f32 " \
                 "{%0,%1,%2,%3}, {%4,%5,%6,%7}, {%8,%9}, {%0,%1,%2,%3};" \
                 : "+f"((cr)[0]), "+f"((cr)[1]), "+f"((cr)[2]), "+f"((cr)[3]) \
                 : "r"((a)[0]), "r"((a)[1]), "r"((a)[2]), "r"((a)[3]), "r"(b0v), "r"(b1v))

// ---------------- fused FG + RES kernel: CTA 128(time) x 256(col), 512 thr ----------------
// Stage slot (30720B): A@0 (128x48=6144), Wh@6144 (256x48=12288), Wl@18432 (12288). 4 stages.
// z tile (single fp16): @122880, pitch 272, 34816B.
#define SLOT  30720u
#define ZOFF  122880u
#define ZPIT  272u
#define FS_BYTES (122880 + 34816)

__global__ void __launch_bounds__(512, 1) fgres_kernel(int layer, int dil,
        const float* __restrict__ bf, const float* __restrict__ bg,
        const float* __restrict__ bres) {
    extern __shared__ __align__(16) char sm[];
    const int tid = threadIdx.x, lane = tid & 31, wid = tid >> 5;
    const int wn = wid >> 3, wc = wid & 7;      // 2 time-groups(64) x 8 col-groups(32)
    const int n0 = blockIdx.x * 128;
    const uint32_t smb = smem_u32(sm);

    const __half* Xrh = g_Xh[layer & 1];
    const __half* Xrl = g_Xl[layer & 1];
    __half* Xwh = g_Xh[(layer + 1) & 1];
    __half* Xwl = g_Xl[(layer + 1) & 1];
    const __half* Wb  = g_WFG + (size_t)layer * 2 * 16 * 4096;
    const __half* WRb = g_WRS + (size_t)layer * 8 * 4096;

    uint32_t offA[4], offB[2], offRB;
    {
        int rA = wn * 64 + (lane & 15);
        int cA = (lane >> 4) * 16;
#pragma unroll
        for (int i = 0; i < 4; i++) offA[i] = (uint32_t)((rA + i * 16) * 48 + cA);
        int rB = wc * 32 + (lane >> 4) * 8 + (lane & 7);
        int cB = ((lane >> 3) & 1) * 16;
        offB[0] = (uint32_t)(rB * 48 + cB);
        offB[1] = (uint32_t)((rB + 16) * 48 + cB);
        int rR = wc * 16 + (lane >> 4) * 8 + (lane & 7);
        offRB = (uint32_t)(rR * 48 + cB);
    }

    float acc[4][4][4];
#pragma unroll
    for (int i = 0; i < 4; i++)
#pragma unroll
        for (int j = 0; j < 4; j++)
#pragma unroll
            for (int k = 0; k < 4; k++) acc[i][j][k] = 0.f;

#define FSTAGE(cc, s) do {                                                        \
        if (tid < 256) {   /* A: 128 rows x 32B = 4KB single plane */             \
            int r = tid >> 1, hh = tid & 1;                                       \
            int na = n0 + r, nn = na, sz = 16, ch0;                               \
            if ((cc) < 8) ch0 = (cc) * 16;                                        \
            else {                                                                \
                ch0 = ((cc) - 8) * 16;                                            \
                int t = na & (T_LEN - 1);                                         \
                if (t >= dil) nn = na - dil; else sz = 0;                         \
            }                                                                     \
            uint32_t d = smb + (s) * SLOT + r * 48u + hh * 16u;                   \
            const __half* gp = Xrh + (size_t)nn * 128 + ch0 + hh * 8;             \
            CPA16(d, gp, sz);                                                     \
        }                                                                         \
        _Pragma("unroll")                                                         \
        for (int ii = 0; ii < 2; ii++) {   /* W: 2 planes x 256 rows x 32B = 16KB */ \
            int u = tid + ii * 512, p = (u >> 9) & 1, r = (u >> 1) & 255, hh = u & 1; \
            uint32_t d = smb + (s) * SLOT + 6144u + p * 12288u + r * 48u + hh * 16u; \
            const __half* sp = Wb + ((size_t)((r >> 7) * 16 + (cc))) * 4096       \
                               + p * 2048 + (r & 127) * 16 + hh * 8;              \
            CPA16(d, sp, 16);                                                     \
        }                                                                         \
    } while (0)

    FSTAGE(0, 0); CP_COMMIT();
    FSTAGE(1, 1); CP_COMMIT();
    FSTAGE(2, 2); CP_COMMIT();

#pragma unroll 1
    for (int c = 0; c < 16; c++) {
        CP_WAIT2();
        __syncthreads();
        if (c + 3 < 16) FSTAGE(c + 3, (c + 3) & 3);
        CP_COMMIT();

        const uint32_t base = smb + (uint32_t)(c & 3) * SLOT;
        uint32_t Ah[4][4], Bf[2][4];
#pragma unroll
        for (int i = 0; i < 4; i++) LDM4(Ah[i], base + offA[i]);
        LDM4(Bf[0], base + 6144u + offB[0]);
        LDM4(Bf[1], base + 6144u + offB[1]);
#pragma unroll
        for (int i = 0; i < 4; i++)
#pragma unroll
            for (int j = 0; j < 4; j++)
                MMA(acc[i][j], Ah[i], Bf[j >> 1][(j & 1) * 2], Bf[j >> 1][(j & 1) * 2 + 1]);
        LDM4(Bf[0], base + 18432u + offB[0]);
        LDM4(Bf[1], base + 18432u + offB[1]);
#pragma unroll
        for (int i = 0; i < 4; i++)
#pragma unroll
            for (int j = 0; j < 4; j++)
                MMA(acc[i][j], Ah[i], Bf[j >> 1][(j & 1) * 2], Bf[j >> 1][(j & 1) * 2 + 1]);
    }
#undef FSTAGE

    // RES W prefetch (overlaps z epilogue). Stage: Wh@0 (128x48), Wl@6144.
#define RSTAGE(rc, s) do {                                                        \
        int p = tid >> 8, r = (tid >> 1) & 127, hh = tid & 1;                     \
        uint32_t d = smb + (s) * SLOT + p * 6144u + r * 48u + hh * 16u;           \
        const __half* sp = WRb + (size_t)(rc) * 4096 + p * 2048 + r * 16 + hh * 8; \
        CPA16(d, sp, 16);                                                         \
    } while (0)

    __syncthreads();   // all FG reads of stage slots done before RES W overwrites
    RSTAGE(0, 0); CP_COMMIT();
    RSTAGE(1, 1); CP_COMMIT();
    RSTAGE(2, 2); CP_COMMIT();

    // ---- epilogue 1: z = tanh(f+bf)*sigmoid(g+bg) -> SMEM z tile + g_Z ----
#pragma unroll
    for (int j = 0; j < 4; j++) {
        int c0 = wc * 32 + j * 8 + (lane & 3) * 2;
        int ch = c0 >> 1;
        float bfv = 0.f, bgv = 0.f;
        if (ch < 120) { bfv = bf[layer * 120 + ch]; bgv = bg[layer * 120 + ch]; }
#pragma unroll
        for (int i = 0; i < 4; i++)
#pragma unroll
            for (int h = 0; h < 2; h++) {
                int row = wn * 64 + i * 16 + h * 8 + (lane >> 2);
                float z = safe_tanh(acc[i][j][h * 2] + bfv) *
                          sigmoidf_(acc[i][j][h * 2 + 1] + bgv);
                __half zh = __float2half(z);
                *reinterpret_cast<__half*>(sm + ZOFF + row * ZPIT + ch * 2) = zh;
                g_Z[(size_t)layer * NTOT * 128 + (size_t)(n0 + row) * 128 + ch] = zh;
            }
    }

    // ---- RES GEMM: racc[128t x 128ch] = z @ Wres^T (z from SMEM) ----
    float racc[4][2][4];
#pragma unroll
    for (int i = 0; i < 4; i++)
#pragma unroll
        for (int j = 0; j < 2; j++)
#pragma unroll
            for (int k = 0; k < 4; k++) racc[i][j][k] = 0.f;

#pragma unroll 1
    for (int rc = 0; rc < 8; rc++) {
        CP_WAIT2();
        __syncthreads();
        if (rc + 3 < 8) RSTAGE(rc + 3, (rc + 3) & 3);
        CP_COMMIT();

        const uint32_t base = smb + (uint32_t)(rc & 3) * SLOT;
        uint32_t ZA[4][4], RB[4];
        uint32_t zk = (uint32_t)(rc * 32) + (lane >> 4) * 16;
#pragma unroll
        for (int i = 0; i < 4; i++) {
            uint32_t zr = smb + ZOFF + (wn * 64 + i * 16 + (lane & 15)) * ZPIT + zk;
            LDM4(ZA[i], zr);
        }
        LDM4(RB, base + offRB);
#pragma unroll
        for (int i = 0; i < 4; i++)
#pragma unroll
            for (int j = 0; j < 2; j++)
                MMA(racc[i][j], ZA[i], RB[j * 2], RB[j * 2 + 1]);
        LDM4(RB, base + 6144u + offRB);
#pragma unroll
        for (int i = 0; i < 4; i++)
#pragma unroll
            for (int j = 0; j < 2; j++)
                MMA(racc[i][j], ZA[i], RB[j * 2], RB[j * 2 + 1]);
    }
#undef RSTAGE

    // ---- epilogue 2: X_next = (Xh+Xl) + res + bres, stored split ----
#pragma unroll
    for (int j = 0; j < 2; j++) {
        int col = wc * 16 + j * 8 + (lane & 3) * 2;
        if (col < 120) {
            float bv0 = bres[layer * 120 + col];
            float bv1 = bres[layer * 120 + col + 1];
#pragma unroll
            for (int i = 0; i < 4; i++)
#pragma unroll
                for (int h = 0; h < 2; h++) {
                    int row = n0 + wn * 64 + i * 16 + h * 8 + (lane >> 2);
                    size_t off = (size_t)row * 128 + col;
                    __half2 xh = *reinterpret_cast<const __half2*>(Xrh + off);
                    __half2 xl = *reinterpret_cast<const __half2*>(Xrl + off);
                    float x0 = __half2float(xh.x) + __half2float(xl.x)
                             + racc[i][j][h * 2] + bv0;
                    float x1 = __half2float(xh.y) + __half2float(xl.y)
                             + racc[i][j][h * 2 + 1] + bv1;
                    __half h0, l0, h1, l1;
                    hsplit(x0, h0, l0); hsplit(x1, h1, l1);
                    __half2 hp; hp.x = h0; hp.y = h1;
                    __half2 lp; lp.x = l0; lp.y = l1;
                    *reinterpret_cast<__half2*>(Xwh + off) = hp;
                    *reinterpret_cast<__half2*>(Xwl + off) = lp;
                }
        }
    }
}

// ---------------- generic GEMM (SKIP / H1 / H2): CTA 128 x 256, 512 thr ----------------
template<int MODE, int NCH>
__global__ void __launch_bounds__(512, 1) mma_kernel(const float* __restrict__ bA,
                                                     float* __restrict__ dout) {
    extern __shared__ __align__(16) char sm[];
    const int tid = threadIdx.x, lane = tid & 31, wid = tid >> 5;
    const int wn = wid >> 3, wc = wid & 7;
    const int n0 = blockIdx.x * 128;
    const uint32_t smb = smem_u32(sm);

    const __half *Wfam, *AP;
    int NB, CHW;
    if (MODE == 2)      { Wfam = g_WSK; NB = 128; AP = g_Z; CHW = 128; }
    else if (MODE == 3) { Wfam = g_W1b; NB = 16;  AP = g_S; CHW = 256; }
    else                { Wfam = g_W2b; NB = 16;  AP = g_H; CHW = 256; }

    uint32_t offA[4], offB[2];
    {
        int rA = wn * 64 + (lane & 15);
        int cA = (lane >> 4) * 16;
#pragma unroll
        for (int i = 0; i < 4; i++) offA[i] = (uint32_t)((rA + i * 16) * 48 + cA);
        int rB = wc * 32 + (lane >> 4) * 8 + (lane & 7);
        int cB = ((lane >> 3) & 1) * 16;
        offB[0] = (uint32_t)(rB * 48 + cB);
        offB[1] = (uint32_t)((rB + 16) * 48 + cB);
    }

    float acc[4][4][4];
#pragma unroll
    for (int i = 0; i < 4; i++)
#pragma unroll
        for (int j = 0; j < 4; j++)
#pragma unroll
            for (int k = 0; k < 4; k++) acc[i][j][k] = 0.f;

#define STAGE(cc, s) do {                                                         \
        if (tid < 256) {                                                          \
            int r = tid >> 1, hh = tid & 1;                                       \
            int ch0; const __half* ap = AP;                                       \
            if (MODE == 2) {                                                      \
                ch0 = ((cc) & 7) * 16;                                            \
                ap += (size_t)((cc) >> 3) * NTOT * 128;                           \
            } else ch0 = (cc) * 16;                                               \
            uint32_t d = smb + (s) * SLOT + r * 48u + hh * 16u;                   \
            CPA16(d, ap + (size_t)(n0 + r) * CHW + ch0 + hh * 8, 16);             \
        }                                                                         \
        _Pragma("unroll")                                                         \
        for (int ii = 0; ii < 2; ii++) {                                          \
            int u = tid + ii * 512, p = (u >> 9) & 1, r = (u >> 1) & 255, hh = u & 1; \
            uint32_t d = smb + (s) * SLOT + 6144u + p * 12288u + r * 48u + hh * 16u; \
            const __half* sp = Wfam + ((size_t)((r >> 7) * NB + (cc))) * 4096     \
                               + p * 2048 + (r & 127) * 16 + hh * 8;              \
            CPA16(d, sp, 16);                                                     \
        }                                                                         \
    } while (0)

    STAGE(0, 0); CP_COMMIT();
    STAGE(1, 1); CP_COMMIT();
    STAGE(2, 2); CP_COMMIT();

#pragma unroll 1
    for (int c = 0; c < NCH; c++) {
        CP_WAIT2();
        __syncthreads();
        if (c + 3 < NCH) STAGE(c + 3, (c + 3) & 3);
        CP_COMMIT();

        const uint32_t base = smb + (uint32_t)(c & 3) * SLOT;
        uint32_t Ah[4][4], Bf[2][4];
#pragma unroll
        for (int i = 0; i < 4; i++) LDM4(Ah[i], base + offA[i]);
        LDM4(Bf[0], base + 6144u + offB[0]);
        LDM4(Bf[1], base + 6144u + offB[1]);
#pragma unroll
        for (int i = 0; i < 4; i++)
#pragma unroll
            for (int j = 0; j < 4; j++)
                MMA(acc[i][j], Ah[i], Bf[j >> 1][(j & 1) * 2], Bf[j >> 1][(j & 1) * 2 + 1]);
        LDM4(Bf[0], base + 18432u + offB[0]);
        LDM4(Bf[1], base + 18432u + offB[1]);
#pragma unroll
        for (int i = 0; i < 4; i++)
#pragma unroll
            for (int j = 0; j < 4; j++)
                MMA(acc[i][j], Ah[i], Bf[j >> 1][(j & 1) * 2], Bf[j >> 1][(j & 1) * 2 + 1]);
    }
#undef STAGE

#pragma unroll
    for (int j = 0; j < 4; j++) {
        const int col = wc * 32 + j * 8 + (lane & 3) * 2;
        float bv0, bv1;
        if (MODE == 2) { bv0 = g_Bsk[col]; bv1 = g_Bsk[col + 1]; }
        else           { bv0 = bA[col]; bv1 = bA[col + 1]; }
#pragma unroll
        for (int i = 0; i < 4; i++)
#pragma unroll
            for (int h = 0; h < 2; h++) {
                int na = n0 + wn * 64 + i * 16 + h * 8 + (lane >> 2);
                float v0 = acc[i][j][h * 2] + bv0, v1 = acc[i][j][h * 2 + 1] + bv1;
                if (MODE == 2 || MODE == 3) {
                    __half2 o;
                    o.x = __float2half(fmaxf(v0, 0.f));
                    o.y = __float2half(fmaxf(v1, 0.f));
                    __half* O = (MODE == 2) ? g_S : g_H;
                    *reinterpret_cast<__half2*>(O + (size_t)na * 256 + col) = o;
                } else {
                    int b = na >> 14, t = na & (T_LEN - 1);
                    dout[((size_t)b * 256 + col) * T_LEN + t]     = v0;
                    dout[((size_t)b * 256 + col + 1) * T_LEN + t] = v1;
                }
            }
    }
}

// ---------------- launch ----------------
extern "C" void kernel_launch(void* const* d_in, const int* in_sizes, int n_in,
                              void* d_out, int out_size) {
    const float* wave  = (const float*)d_in[0];
    const float* W_in  = (const float*)d_in[1];
    const float* b_in  = (const float*)d_in[2];
    const float* Wf    = (const float*)d_in[3];
    const float* bf    = (const float*)d_in[4];
    const float* Wg    = (const float*)d_in[5];
    const float* bg    = (const float*)d_in[6];
    const float* Wres  = (const float*)d_in[7];
    const float* bres  = (const float*)d_in[8];
    const float* Wskip = (const float*)d_in[9];
    const float* bskip = (const float*)d_in[10];
    const float* W1    = (const float*)d_in[11];
    const float* b1    = (const float*)d_in[12];
    const float* W2    = (const float*)d_in[13];
    const float* b2    = (const float*)d_in[14];
    float* out = (float*)d_out;

    const int GS = 4 * SLOT;   // 122880 for generic kernels
    cudaFuncSetAttribute(fgres_kernel, cudaFuncAttributeMaxDynamicSharedMemorySize, FS_BYTES);
    cudaFuncSetAttribute(mma_kernel<2, 128>, cudaFuncAttributeMaxDynamicSharedMemorySize, GS);
    cudaFuncSetAttribute(mma_kernel<3, 16>,  cudaFuncAttributeMaxDynamicSharedMemorySize, GS);
    cudaFuncSetAttribute(mma_kernel<4, 16>,  cudaFuncAttributeMaxDynamicSharedMemorySize, GS);

    pack_fg<<<16 * 2 * 16 * 2048 / 256, 256>>>(Wf, Wg);
    pack_rs<<<16 * 8 * 2048 / 256, 256>>>(Wres);
    pack_sk<<<2 * 128 * 2048 / 256, 256>>>(Wskip, bskip);
    pack_h <<<2 * 16 * 2048 / 256, 256>>>(W1, W2);
    init_kernel<<<(size_t)NTOT * 128 / 256, 256>>>(wave, W_in, b_in);

    static const int dil[NBLK] = {1, 2, 4, 8, 16, 32, 64, 128,
                                  1, 2, 4, 8, 16, 32, 64, 128};

    for (int i = 0; i < NBLK; i++)
        fgres_kernel<<<NTOT / 128, 512, FS_BYTES>>>(i, dil[i], bf, bg, bres);

    mma_kernel<2, 128><<<NTOT / 128, 512, GS>>>(nullptr, nullptr);  // batched skip
    mma_kernel<3, 16><<<NTOT / 128, 512, GS>>>(b1, nullptr);        // head1
    mma_kernel<4, 16><<<NTOT / 128, 512, GS>>>(b2, out);            // head2
}